// round 16
// baseline (speedup 1.0000x reference)
#include <cuda_runtime.h>
#include <cuda_fp16.h>
#include <cstdint>

#define BATCH 32
#define NFACT 64
#define DOBJ  128
#define GH    256
#define FOUT  32

// ---------------- scratch (__device__ globals; no allocs allowed) ------------
__device__ float  g_Ue[BATCH * NFACT * GH];
__device__ float  g_Vv[BATCH * NFACT * GH];
__device__ float  g_emb[BATCH * GH];   // atomically accumulated embedding
__device__ __half g_W1h[GH * GH];      // [n][k] = half(W1[k][n])
__device__ __half g_W2h[GH * GH];      // [n][k] = half(W2[k][n])

// ---------------- SMEM layout of rn_mma_kernel -------------------------------
#define AS_STRIDE_H 264
#define WROW_B 144
#define OFF_B1 0
#define OFF_B2 1024
#define OFF_RED 2048                       // [4][256] floats = 4096 B
#define OFF_A  6144
#define A_BYTES (128 * AS_STRIDE_H * 2)    // 67584
#define OFF_W  (OFF_A + A_BYTES)           // 73728
#define WBUF_B (GH * WROW_B)               // 36864 B
#define SMEM_TOT (OFF_W + 3 * WBUF_B)      // 184320 B -> 1 CTA/SM

// ---------------- SMEM layout of prep_kernel (dynamic; floats) ---------------
#define P_XS   0                           // 64x128 x tile (8192 floats)
#define P_WS   8192                        // ws_t[32][132] transposed W slab
#define P_QRED 12416                       // 8x32
#define P_QCS  12672                       // 32
#define PREP_SMEM ((12704) * 4)            // 50816 B -> 4 CTAs/SM

// ---------------- helpers ----------------------------------------------------
__device__ __forceinline__ uint32_t smem_u32(const void* p) {
    uint32_t a;
    asm("{ .reg .u64 t; cvta.to.shared.u64 t, %1; cvt.u32.u64 %0, t; }" : "=r"(a) : "l"(p));
    return a;
}
__device__ __forceinline__ void cp_async16(uint32_t s, const void* g) {
    asm volatile("cp.async.cg.shared.global [%0], [%1], 16;" :: "r"(s), "l"(g));
}
__device__ __forceinline__ void cp_commit() {
    asm volatile("cp.async.commit_group;" ::: "memory");
}
__device__ __forceinline__ void mma16(float c[4], const uint32_t a[4], const uint32_t b[2]) {
    asm volatile(
        "mma.sync.aligned.m16n8k16.row.col.f32.f16.f16.f32 "
        "{%0,%1,%2,%3}, {%4,%5,%6,%7}, {%8,%9}, {%0,%1,%2,%3};"
        : "+f"(c[0]), "+f"(c[1]), "+f"(c[2]), "+f"(c[3])
        : "r"(a[0]), "r"(a[1]), "r"(a[2]), "r"(a[3]), "r"(b[0]), "r"(b[1]));
}
__device__ __forceinline__ void ldsm_x4(uint32_t r[4], uint32_t addr) {
    asm volatile(
        "ldmatrix.sync.aligned.m8n8.x4.shared.b16 {%0,%1,%2,%3}, [%4];"
        : "=r"(r[0]), "=r"(r[1]), "=r"(r[2]), "=r"(r[3]) : "r"(addr));
}
__device__ __forceinline__ uint32_t pack_h2(float lo, float hi) {
    __half2 h = __floats2half2_rn(lo, hi);
    return *(uint32_t*)&h;
}

// ---------------- K1: prep ---------------------------------------------------
// blocks [0,128): transpose W1/W2 -> half [n][k]; blocks [0,8) also zero g_emb.
// blocks [128,640): uv 64x32 chunks; W slab transposed in SMEM for LDS.128.
__global__ __launch_bounds__(256, 4) void prep_kernel(const float* __restrict__ x,
                                                      const float* __restrict__ q,
                                                      const float* __restrict__ w0,
                                                      const float* __restrict__ b0,
                                                      const float* __restrict__ w1,
                                                      const float* __restrict__ w2) {
    extern __shared__ float psm[];
    float* xs = psm + P_XS;
    float* wst = psm + P_WS;      // [32 cols][132] (col-major W slab)
    float* qred = psm + P_QRED;
    float* qcs = psm + P_QCS;
    int tid = threadIdx.x;

    if (blockIdx.x < 128) {
        if (blockIdx.x < 8) {
            float4 z = {0.f, 0.f, 0.f, 0.f};
            *(float4*)&g_emb[(blockIdx.x * 256 + tid) * 4] = z;
        }
        int bid = blockIdx.x;
        int z = bid >> 6, rem = bid & 63;
        int bx = (rem & 7) * 32, by = (rem >> 3) * 32;
        const float* in = z ? w2 : w1;
        __half* out = z ? g_W2h : g_W1h;
        float (*tile)[33] = (float (*)[33])xs;
        int tx = tid & 31, ty = tid >> 5;
#pragma unroll
        for (int r = ty; r < 32; r += 8)
            tile[r][tx] = in[(by + r) * GH + bx + tx];
        __syncthreads();
#pragma unroll
        for (int r = ty; r < 32; r += 8)
            out[(bx + r) * GH + by + tx] = __float2half_rn(tile[tx][r]);
        return;
    }

    int uvid = blockIdx.x - 128;
    int cc = uvid & 7, part = (uvid >> 3) & 1, b = uvid >> 4;

    // stage x[b] (64x128) and transposed W slab
    const float4* xb = (const float4*)(x + b * NFACT * DOBJ);
#pragma unroll
    for (int i = 0; i < 8; i++) ((float4*)xs)[tid + i * 256] = xb[tid + i * 256];
    const float* wbase = w0 + part * DOBJ * GH + cc * 32;
#pragma unroll
    for (int i = 0; i < 4; i++) {
        int p = tid + i * 256;          // 1024 slots: 128 rows x 8 col-groups
        int row = p >> 3, c4 = p & 7;
        float4 v = *(const float4*)(wbase + row * GH + c4 * 4);
        wst[(c4 * 4 + 0) * 132 + row] = v.x;
        wst[(c4 * 4 + 1) * 132 + row] = v.y;
        wst[(c4 * 4 + 2) * 132 + row] = v.z;
        wst[(c4 * 4 + 3) * 132 + row] = v.w;
    }
    if (part == 0) {  // qc for this block's 32 cols: 8 threads per col x 16 k
        int colL = tid & 31, seg = tid >> 5;
        int colG = cc * 32 + colL;
        const float* qr = q + b * DOBJ;
        float s = 0.f;
#pragma unroll 8
        for (int k = 0; k < 16; k++) {
            int kk = seg * 16 + k;
            s = fmaf(qr[kk], w0[(2 * DOBJ + kk) * GH + colG], s);
        }
        qred[seg * 32 + colL] = s;
    }
    __syncthreads();
    if (part == 0 && tid < 32) {
        float t = 0.f;
#pragma unroll
        for (int s = 0; s < 8; s++) t += qred[s * 32 + tid];
        qcs[tid] = b0[cc * 32 + tid] + t;
    }
    __syncthreads();

    int ty = tid >> 5, tx = tid & 31;
    const float4* xs4 = (const float4*)xs;
    const float* wt = wst + tx * 132;   // this thread's W column
    float acc[8];
#pragma unroll
    for (int r = 0; r < 8; r++) acc[r] = 0.f;
#pragma unroll 2
    for (int k4 = 0; k4 < 32; k4++) {
        float4 a4[8];
#pragma unroll
        for (int r = 0; r < 8; r++) a4[r] = xs4[(ty + 8 * r) * 32 + k4];
        float4 w4 = *(const float4*)(wt + 4 * k4);
#pragma unroll
        for (int r = 0; r < 8; r++) {
            acc[r] = fmaf(a4[r].x, w4.x, acc[r]);
            acc[r] = fmaf(a4[r].y, w4.y, acc[r]);
            acc[r] = fmaf(a4[r].z, w4.z, acc[r]);
            acc[r] = fmaf(a4[r].w, w4.w, acc[r]);
        }
    }
    float* outp = (part == 0) ? g_Ue : g_Vv;
#pragma unroll
    for (int r = 0; r < 8; r++) {
        int row = ty + 8 * r;
        float v = acc[r];
        if (part == 0) v += qcs[tx];
        outp[(b * NFACT + row) * GH + cc * 32 + tx] = v;
    }
}

// ---------------- K2: fp16 mma.sync fused kernel (LDSM mainloop) -------------
__device__ __forceinline__ void load_w_chunk(uint32_t su, const __half* __restrict__ Wh,
                                             int kc, int buf) {
    const __half* src = Wh + kc * 64;
    uint32_t dst = su + OFF_W + buf * WBUF_B;
#pragma unroll
    for (int i = 0; i < 4; i++) {
        int p = threadIdx.x + i * 512;  // 2048 slots: 256 n-rows x 8 x 16B
        int n = p >> 3, c4 = p & 7;
        cp_async16(dst + n * WROW_B + c4 * 16, src + n * GH + c4 * 8);
    }
    cp_commit();
}

// one 128x256x256 fp16 GEMM: 4 chunks of k=64 over a 3-buffer ring (hazard
// proof as R12). Fragment loads via ldmatrix.x4 (map == mma fragment map).
// No trailing sync — caller syncs before reusing A or W.
__device__ __forceinline__ void gemm_mma(uint32_t su, const __half* __restrict__ Wh,
                                         int sb, const uint32_t aA[2],
                                         const uint32_t bB[4], float c[2][8][4]) {
#pragma unroll 1
    for (int kc = 0; kc < 4; kc++) {
        if (kc < 3) asm volatile("cp.async.wait_group 1;" ::: "memory");
        else        asm volatile("cp.async.wait_group 0;" ::: "memory");
        __syncthreads();
        if (kc < 2) load_w_chunk(su, Wh, kc + 2, (sb + kc + 2) % 3);
        uint32_t bufofs = (uint32_t)(((sb + kc) % 3) * WBUF_B);
#pragma unroll
        for (int ks = 0; ks < 4; ks++) {
            uint32_t kofs = kc * 128 + ks * 32;  // bytes into A k-dim
            uint32_t a0[4], a1[4];
            ldsm_x4(a0, aA[0] + kofs);
            ldsm_x4(a1, aA[1] + kofs);
#pragma unroll
            for (int p = 0; p < 4; p++) {
                uint32_t bb[4];
                ldsm_x4(bb, bB[p] + bufofs + ks * 32);
                mma16(c[0][2 * p],     a0, &bb[0]);
                mma16(c[1][2 * p],     a1, &bb[0]);
                mma16(c[0][2 * p + 1], a0, &bb[2]);
                mma16(c[1][2 * p + 1], a1, &bb[2]);
            }
        }
    }
}

__global__ __launch_bounds__(512, 1) void rn_mma_kernel(const float* __restrict__ b1g,
                                                        const float* __restrict__ b2g) {
    extern __shared__ char smc[];
    uint32_t su = smem_u32(smc);
    __half* As = (__half*)(smc + OFF_A);
    float* b1s = (float*)(smc + OFF_B1);
    float* b2s = (float*)(smc + OFF_B2);
    float* red = (float*)(smc + OFF_RED);  // [4][256]

    int tid = threadIdx.x, lane = tid & 31, wid = tid >> 5;
    int gid = lane >> 2, tig = lane & 3;
    int mw = wid & 3, nw = wid >> 2;
    int m0 = mw * 32, n0 = nw * 64;
    int b = blockIdx.x >> 5, jp = blockIdx.x & 31;

    // per-lane ldmatrix base addresses
    int mi = lane >> 3, rowin = lane & 7;
    uint32_t aA[2], bB[4];
#pragma unroll
    for (int mt = 0; mt < 2; mt++)
        aA[mt] = su + OFF_A +
                 (uint32_t)((m0 + mt * 16 + (mi & 1) * 8 + rowin) * (AS_STRIDE_H * 2)) +
                 (uint32_t)((mi >> 1) * 16);
#pragma unroll
    for (int p = 0; p < 4; p++)
        bB[p] = su + OFF_W +
                (uint32_t)((n0 + (2 * p + (mi >> 1)) * 8 + rowin) * WROW_B) +
                (uint32_t)((mi & 1) * 16);

    if (tid < GH) {
        b1s[tid] = b1g[tid];
        b2s[tid] = b2g[tid];
    }

    load_w_chunk(su, g_W1h, 0, 0);
    load_w_chunk(su, g_W1h, 1, 1);

    // ---- build h0: rows [0,64) = (j0, i), rows [64,128) = (j1, i) ----
    {
        const float4* UeB = (const float4*)(g_Ue + b * NFACT * GH);
        const float4* VvB = (const float4*)(g_Vv + (b * NFACT + 2 * jp) * GH);
#pragma unroll
        for (int it = 0; it < 16; it++) {
            int p = tid + it * 512;
            int r = p >> 6, c4 = p & 63;
            int i = r & 63, jl = r >> 6;
            float4 u = UeB[i * 64 + c4];
            float4 v = VvB[jl * 64 + c4];
            uint2 o;
            o.x = pack_h2(fmaxf(u.x + v.x, 0.f), fmaxf(u.y + v.y, 0.f));
            o.y = pack_h2(fmaxf(u.z + v.z, 0.f), fmaxf(u.w + v.w, 0.f));
            *(uint2*)((char*)smc + OFF_A + r * (AS_STRIDE_H * 2) + c4 * 8) = o;
        }
    }

    float c[2][8][4];
#pragma unroll
    for (int mt = 0; mt < 2; mt++)
#pragma unroll
        for (int nt = 0; nt < 8; nt++)
#pragma unroll
            for (int q = 0; q < 4; q++) c[mt][nt][q] = 0.f;

    // ---- GEMM1: D1 = h0 @ W1 (sb=0) ----
    gemm_mma(su, g_W1h, 0, aA, bB, c);

    load_w_chunk(su, g_W2h, 0, 1);   // buf1 free (last read G1 kc=1)
    __syncthreads();
    load_w_chunk(su, g_W2h, 1, 2);

    // ---- epilogue1: h1 = half(relu(D1 + b1)) -> A ----
#pragma unroll
    for (int mt = 0; mt < 2; mt++)
#pragma unroll
        for (int nt = 0; nt < 8; nt++) {
            int r = m0 + mt * 16 + gid, col = n0 + nt * 8 + 2 * tig;
            float bb0 = b1s[col], bb1 = b1s[col + 1];
            *(uint32_t*)(As + r * AS_STRIDE_H + col) =
                pack_h2(fmaxf(c[mt][nt][0] + bb0, 0.f), fmaxf(c[mt][nt][1] + bb1, 0.f));
            *(uint32_t*)(As + (r + 8) * AS_STRIDE_H + col) =
                pack_h2(fmaxf(c[mt][nt][2] + bb0, 0.f), fmaxf(c[mt][nt][3] + bb1, 0.f));
            c[mt][nt][0] = c[mt][nt][1] = c[mt][nt][2] = c[mt][nt][3] = 0.f;
        }

    // ---- GEMM2: D2 = h1 @ W2 (sb=1) ----
    gemm_mma(su, g_W2h, 1, aA, bB, c);

    // ---- epilogue2: relu(D2 + b2), shuffle-reduce, atomicAdd to g_emb ----
    {
        int jl = mw >> 1, sub = mw & 1;
#pragma unroll
        for (int nt = 0; nt < 8; nt++) {
            int col = n0 + nt * 8 + 2 * tig;
            float bb0 = b2s[col], bb1 = b2s[col + 1];
            float s0 = fmaxf(c[0][nt][0] + bb0, 0.f) + fmaxf(c[0][nt][2] + bb0, 0.f) +
                       fmaxf(c[1][nt][0] + bb0, 0.f) + fmaxf(c[1][nt][2] + bb0, 0.f);
            float s1 = fmaxf(c[0][nt][1] + bb1, 0.f) + fmaxf(c[0][nt][3] + bb1, 0.f) +
                       fmaxf(c[1][nt][1] + bb1, 0.f) + fmaxf(c[1][nt][3] + bb1, 0.f);
#pragma unroll
            for (int msk = 4; msk <= 16; msk <<= 1) {
                s0 += __shfl_xor_sync(0xFFFFFFFF, s0, msk);
                s1 += __shfl_xor_sync(0xFFFFFFFF, s1, msk);
            }
            if (gid == 0) {
                red[(jl * 2 + sub) * GH + col] = s0;
                red[(jl * 2 + sub) * GH + col + 1] = s1;
            }
        }
        __syncthreads();
        if (tid < GH) {
            float t = (red[tid] + red[GH + tid]) + (red[2 * GH + tid] + red[3 * GH + tid]);
            atomicAdd(&g_emb[b * GH + tid], t);
        }
    }
}

// ---------------- K3: f MLP (reads g_emb directly) ---------------------------
__global__ __launch_bounds__(256) void f_kernel(const float* __restrict__ fw0,
                                                const float* __restrict__ fb0,
                                                const float* __restrict__ fw1,
                                                const float* __restrict__ fb1,
                                                float* __restrict__ out) {
    __shared__ float e[GH];
    __shared__ float h[GH];
    __shared__ float red[8 * FOUT];
    int b = blockIdx.x, tid = threadIdx.x;

    e[tid] = g_emb[b * GH + tid];
    __syncthreads();

    {
        float a[8];
#pragma unroll
        for (int u = 0; u < 8; u++) a[u] = 0.f;
#pragma unroll 4
        for (int k = 0; k < GH; k += 8)
#pragma unroll
            for (int u = 0; u < 8; u++)
                a[u] = fmaf(e[k + u], fw0[(k + u) * GH + tid], a[u]);
        float t = ((a[0] + a[1]) + (a[2] + a[3])) + ((a[4] + a[5]) + (a[6] + a[7]));
        h[tid] = fmaxf(t + fb0[tid], 0.f);
    }
    __syncthreads();

    {
        int w = tid >> 5, lane = tid & 31;
        float ps = 0.f;
#pragma unroll
        for (int kk = 0; kk < 32; kk++) {
            int k = w * 32 + kk;
            ps = fmaf(h[k], fw1[k * FOUT + lane], ps);
        }
        red[w * FOUT + lane] = ps;
        __syncthreads();
        if (tid < FOUT) {
            float a = fb1[tid];
#pragma unroll
            for (int t = 0; t < 8; t++) a += red[t * FOUT + tid];
            out[b * FOUT + tid] = a;
        }
    }
}

// ---------------- launch ----------------------------------------------------
extern "C" void kernel_launch(void* const* d_in, const int* in_sizes, int n_in,
                              void* d_out, int out_size) {
    const float* x   = (const float*)d_in[0];
    const float* q   = (const float*)d_in[1];
    const float* gw0 = (const float*)d_in[2];
    const float* gb0 = (const float*)d_in[3];
    const float* gw1 = (const float*)d_in[4];
    const float* gb1 = (const float*)d_in[5];
    const float* gw2 = (const float*)d_in[6];
    const float* gb2 = (const float*)d_in[7];
    const float* fw0 = (const float*)d_in[8];
    const float* fb0 = (const float*)d_in[9];
    const float* fw1 = (const float*)d_in[10];
    const float* fb1 = (const float*)d_in[11];
    float* out = (float*)d_out;

    cudaFuncSetAttribute(rn_mma_kernel, cudaFuncAttributeMaxDynamicSharedMemorySize, SMEM_TOT);
    cudaFuncSetAttribute(prep_kernel, cudaFuncAttributeMaxDynamicSharedMemorySize, PREP_SMEM);

    prep_kernel<<<640, 256, PREP_SMEM>>>(x, q, gw0, gb0, gw1, gw2);
    rn_mma_kernel<<<BATCH * NFACT / 2, 512, SMEM_TOT>>>(gb1, gb2);
    f_kernel<<<BATCH, 256>>>(fw0, fb0, fw1, fb1, out);
}

// round 17
// speedup vs baseline: 1.0365x; 1.0365x over previous
#include <cuda_runtime.h>
#include <cuda_fp16.h>
#include <cstdint>

#define BATCH 32
#define NFACT 64
#define DOBJ  128
#define GH    256
#define FOUT  32

// ---------------- scratch (__device__ globals; no allocs allowed) ------------
__device__ float  g_Ue[BATCH * NFACT * GH];
__device__ float  g_Vv[BATCH * NFACT * GH];
__device__ float  g_emb[BATCH * GH];   // atomically accumulated embedding
__device__ __half g_W1h[GH * GH];      // [n][k] = half(W1[k][n])
__device__ __half g_W2h[GH * GH];      // [n][k] = half(W2[k][n])

// ---------------- SMEM layout of rn_mma_kernel -------------------------------
#define AS_STRIDE_H 264
#define WROW_B 144
#define OFF_B1 0
#define OFF_B2 1024
#define OFF_RED 2048                       // [4][256] floats = 4096 B
#define OFF_A  6144
#define A_BYTES (128 * AS_STRIDE_H * 2)    // 67584
#define OFF_W  (OFF_A + A_BYTES)           // 73728
#define WBUF_B (GH * WROW_B)               // 36864 B
#define SMEM_TOT (OFF_W + 3 * WBUF_B)      // 184320 B -> 1 CTA/SM

// ---------------- SMEM layout of prep_kernel (dynamic; floats) ---------------
#define P_XS   0                           // 64x128 x tile (8192 floats)
#define P_WS   8192                        // [128 rows][32 cols] W slab
#define P_QRED 12288                       // 8x32
#define P_QCS  12544                       // 32
#define PREP_SMEM ((12576) * 4)            // 50304 B -> 4 CTAs/SM

// ---------------- helpers ----------------------------------------------------
__device__ __forceinline__ uint32_t smem_u32(const void* p) {
    uint32_t a;
    asm("{ .reg .u64 t; cvta.to.shared.u64 t, %1; cvt.u32.u64 %0, t; }" : "=r"(a) : "l"(p));
    return a;
}
__device__ __forceinline__ void cp_async16(uint32_t s, const void* g) {
    asm volatile("cp.async.cg.shared.global [%0], [%1], 16;" :: "r"(s), "l"(g));
}
__device__ __forceinline__ void cp_commit() {
    asm volatile("cp.async.commit_group;" ::: "memory");
}
__device__ __forceinline__ void mma16(float c[4], const uint32_t a[4], const uint32_t b[2]) {
    asm volatile(
        "mma.sync.aligned.m16n8k16.row.col.f32.f16.f16.f32 "
        "{%0,%1,%2,%3}, {%4,%5,%6,%7}, {%8,%9}, {%0,%1,%2,%3};"
        : "+f"(c[0]), "+f"(c[1]), "+f"(c[2]), "+f"(c[3])
        : "r"(a[0]), "r"(a[1]), "r"(a[2]), "r"(a[3]), "r"(b[0]), "r"(b[1]));
}
__device__ __forceinline__ void ldsm_x4(uint32_t r[4], uint32_t addr) {
    asm volatile(
        "ldmatrix.sync.aligned.m8n8.x4.shared.b16 {%0,%1,%2,%3}, [%4];"
        : "=r"(r[0]), "=r"(r[1]), "=r"(r[2]), "=r"(r[3]) : "r"(addr));
}
__device__ __forceinline__ uint32_t pack_h2(float lo, float hi) {
    __half2 h = __floats2half2_rn(lo, hi);
    return *(uint32_t*)&h;
}

// ---------------- K1: prep ---------------------------------------------------
// blocks [0,128): transpose W1/W2 -> half [n][k]; blocks [0,8) also zero g_emb.
// blocks [128,640): uv 64x32 chunks; staging via cp.async overlapped with qc.
__global__ __launch_bounds__(256) void prep_kernel(const float* __restrict__ x,
                                                   const float* __restrict__ q,
                                                   const float* __restrict__ w0,
                                                   const float* __restrict__ b0,
                                                   const float* __restrict__ w1,
                                                   const float* __restrict__ w2) {
    extern __shared__ float psm[];
    float* xs = psm + P_XS;
    float* ws = psm + P_WS;
    float* qred = psm + P_QRED;
    float* qcs = psm + P_QCS;
    uint32_t su = smem_u32(psm);
    int tid = threadIdx.x;

    if (blockIdx.x < 128) {
        if (blockIdx.x < 8) {
            float4 z = {0.f, 0.f, 0.f, 0.f};
            *(float4*)&g_emb[(blockIdx.x * 256 + tid) * 4] = z;
        }
        int bid = blockIdx.x;
        int z = bid >> 6, rem = bid & 63;
        int bx = (rem & 7) * 32, by = (rem >> 3) * 32;
        const float* in = z ? w2 : w1;
        __half* out = z ? g_W2h : g_W1h;
        float (*tile)[33] = (float (*)[33])xs;
        int tx = tid & 31, ty = tid >> 5;
#pragma unroll
        for (int r = ty; r < 32; r += 8)
            tile[r][tx] = in[(by + r) * GH + bx + tx];
        __syncthreads();
#pragma unroll
        for (int r = ty; r < 32; r += 8)
            out[(bx + r) * GH + by + tx] = __float2half_rn(tile[tx][r]);
        return;
    }

    int uvid = blockIdx.x - 128;
    int cc = uvid & 7, part = (uvid >> 3) & 1, b = uvid >> 4;

    // stage x[b] (64x128) + W slab via cp.async (latency overlaps qc below)
    const float* xb = x + b * NFACT * DOBJ;
#pragma unroll
    for (int i = 0; i < 8; i++) {
        int p = tid + i * 256;          // 2048 float4 slots
        cp_async16(su + (uint32_t)(P_XS * 4) + p * 16, xb + p * 4);
    }
    const float* wbase = w0 + part * DOBJ * GH + cc * 32;
#pragma unroll
    for (int i = 0; i < 4; i++) {
        int p = tid + i * 256;          // 1024 slots: 128 rows x 8 col-groups
        int row = p >> 3, c4 = p & 7;
        cp_async16(su + (uint32_t)(P_WS * 4) + p * 16, wbase + row * GH + c4 * 4);
    }
    cp_commit();

    if (part == 0) {  // qc overlaps the cp.async latency
        int colL = tid & 31, seg = tid >> 5;
        int colG = cc * 32 + colL;
        const float* qr = q + b * DOBJ;
        float s = 0.f;
#pragma unroll 8
        for (int k = 0; k < 16; k++) {
            int kk = seg * 16 + k;
            s = fmaf(qr[kk], w0[(2 * DOBJ + kk) * GH + colG], s);
        }
        qred[seg * 32 + colL] = s;
    }
    asm volatile("cp.async.wait_group 0;" ::: "memory");
    __syncthreads();
    if (part == 0 && tid < 32) {
        float t = 0.f;
#pragma unroll
        for (int s = 0; s < 8; s++) t += qred[s * 32 + tid];
        qcs[tid] = b0[cc * 32 + tid] + t;
    }
    __syncthreads();

    int ty = tid >> 5, tx = tid & 31;
    const float4* xs4 = (const float4*)xs;
    float acc[8];
#pragma unroll
    for (int r = 0; r < 8; r++) acc[r] = 0.f;
#pragma unroll 2
    for (int k4 = 0; k4 < 32; k4++) {
        float4 a4[8];
#pragma unroll
        for (int r = 0; r < 8; r++) a4[r] = xs4[(ty + 8 * r) * 32 + k4];
        float w0v = ws[(4 * k4 + 0) * 32 + tx];
        float w1v = ws[(4 * k4 + 1) * 32 + tx];
        float w2v = ws[(4 * k4 + 2) * 32 + tx];
        float w3v = ws[(4 * k4 + 3) * 32 + tx];
#pragma unroll
        for (int r = 0; r < 8; r++) {
            acc[r] = fmaf(a4[r].x, w0v, acc[r]);
            acc[r] = fmaf(a4[r].y, w1v, acc[r]);
            acc[r] = fmaf(a4[r].z, w2v, acc[r]);
            acc[r] = fmaf(a4[r].w, w3v, acc[r]);
        }
    }
    float* outp = (part == 0) ? g_Ue : g_Vv;
#pragma unroll
    for (int r = 0; r < 8; r++) {
        int row = ty + 8 * r;
        float v = acc[r];
        if (part == 0) v += qcs[tx];
        outp[(b * NFACT + row) * GH + cc * 32 + tx] = v;
    }
}

// ---------------- K2: fp16 mma.sync fused kernel (R15 version) ---------------
__device__ __forceinline__ void load_w_chunk(uint32_t su, const __half* __restrict__ Wh,
                                             int kc, int buf) {
    const __half* src = Wh + kc * 64;
    uint32_t dst = su + OFF_W + buf * WBUF_B;
#pragma unroll
    for (int i = 0; i < 4; i++) {
        int p = threadIdx.x + i * 512;  // 2048 slots: 256 n-rows x 8 x 16B
        int n = p >> 3, c4 = p & 7;
        cp_async16(dst + n * WROW_B + c4 * 16, src + n * GH + c4 * 8);
    }
    cp_commit();
}

// one 128x256x256 fp16 GEMM: 4 chunks of k=64 over a 3-buffer ring (hazard
// proof as R12). Fragment loads via ldmatrix.x4 (map == mma fragment map).
// No trailing sync — caller syncs before reusing A or W.
__device__ __forceinline__ void gemm_mma(uint32_t su, const __half* __restrict__ Wh,
                                         int sb, const uint32_t aA[2],
                                         const uint32_t bB[4], float c[2][8][4]) {
#pragma unroll 1
    for (int kc = 0; kc < 4; kc++) {
        if (kc < 3) asm volatile("cp.async.wait_group 1;" ::: "memory");
        else        asm volatile("cp.async.wait_group 0;" ::: "memory");
        __syncthreads();
        if (kc < 2) load_w_chunk(su, Wh, kc + 2, (sb + kc + 2) % 3);
        uint32_t bufofs = (uint32_t)(((sb + kc) % 3) * WBUF_B);
#pragma unroll
        for (int ks = 0; ks < 4; ks++) {
            uint32_t kofs = kc * 128 + ks * 32;  // bytes into A k-dim
            uint32_t a0[4], a1[4];
            ldsm_x4(a0, aA[0] + kofs);
            ldsm_x4(a1, aA[1] + kofs);
#pragma unroll
            for (int p = 0; p < 4; p++) {
                uint32_t bb[4];
                ldsm_x4(bb, bB[p] + bufofs + ks * 32);
                mma16(c[0][2 * p],     a0, &bb[0]);
                mma16(c[1][2 * p],     a1, &bb[0]);
                mma16(c[0][2 * p + 1], a0, &bb[2]);
                mma16(c[1][2 * p + 1], a1, &bb[2]);
            }
        }
    }
}

__global__ __launch_bounds__(512, 1) void rn_mma_kernel(const float* __restrict__ b1g,
                                                        const float* __restrict__ b2g) {
    extern __shared__ char smc[];
    uint32_t su = smem_u32(smc);
    __half* As = (__half*)(smc + OFF_A);
    float* b1s = (float*)(smc + OFF_B1);
    float* b2s = (float*)(smc + OFF_B2);
    float* red = (float*)(smc + OFF_RED);  // [4][256]

    int tid = threadIdx.x, lane = tid & 31, wid = tid >> 5;
    int gid = lane >> 2, tig = lane & 3;
    int mw = wid & 3, nw = wid >> 2;
    int m0 = mw * 32, n0 = nw * 64;
    int b = blockIdx.x >> 5, jp = blockIdx.x & 31;

    // per-lane ldmatrix base addresses
    int mi = lane >> 3, rowin = lane & 7;
    uint32_t aA[2], bB[4];
#pragma unroll
    for (int mt = 0; mt < 2; mt++)
        aA[mt] = su + OFF_A +
                 (uint32_t)((m0 + mt * 16 + (mi & 1) * 8 + rowin) * (AS_STRIDE_H * 2)) +
                 (uint32_t)((mi >> 1) * 16);
#pragma unroll
    for (int p = 0; p < 4; p++)
        bB[p] = su + OFF_W +
                (uint32_t)((n0 + (2 * p + (mi >> 1)) * 8 + rowin) * WROW_B) +
                (uint32_t)((mi & 1) * 16);

    if (tid < GH) {
        b1s[tid] = b1g[tid];
        b2s[tid] = b2g[tid];
    }

    load_w_chunk(su, g_W1h, 0, 0);
    load_w_chunk(su, g_W1h, 1, 1);

    // ---- build h0: rows [0,64) = (j0, i), rows [64,128) = (j1, i) ----
    {
        const float4* UeB = (const float4*)(g_Ue + b * NFACT * GH);
        const float4* VvB = (const float4*)(g_Vv + (b * NFACT + 2 * jp) * GH);
#pragma unroll
        for (int it = 0; it < 16; it++) {
            int p = tid + it * 512;
            int r = p >> 6, c4 = p & 63;
            int i = r & 63, jl = r >> 6;
            float4 u = UeB[i * 64 + c4];
            float4 v = VvB[jl * 64 + c4];
            uint2 o;
            o.x = pack_h2(fmaxf(u.x + v.x, 0.f), fmaxf(u.y + v.y, 0.f));
            o.y = pack_h2(fmaxf(u.z + v.z, 0.f), fmaxf(u.w + v.w, 0.f));
            *(uint2*)((char*)smc + OFF_A + r * (AS_STRIDE_H * 2) + c4 * 8) = o;
        }
    }

    float c[2][8][4];
#pragma unroll
    for (int mt = 0; mt < 2; mt++)
#pragma unroll
        for (int nt = 0; nt < 8; nt++)
#pragma unroll
            for (int q = 0; q < 4; q++) c[mt][nt][q] = 0.f;

    // ---- GEMM1: D1 = h0 @ W1 (sb=0) ----
    gemm_mma(su, g_W1h, 0, aA, bB, c);

    load_w_chunk(su, g_W2h, 0, 1);   // buf1 free (last read G1 kc=1)
    __syncthreads();
    load_w_chunk(su, g_W2h, 1, 2);

    // ---- epilogue1: h1 = half(relu(D1 + b1)) -> A ----
#pragma unroll
    for (int mt = 0; mt < 2; mt++)
#pragma unroll
        for (int nt = 0; nt < 8; nt++) {
            int r = m0 + mt * 16 + gid, col = n0 + nt * 8 + 2 * tig;
            float bb0 = b1s[col], bb1 = b1s[col + 1];
            *(uint32_t*)(As + r * AS_STRIDE_H + col) =
                pack_h2(fmaxf(c[mt][nt][0] + bb0, 0.f), fmaxf(c[mt][nt][1] + bb1, 0.f));
            *(uint32_t*)(As + (r + 8) * AS_STRIDE_H + col) =
                pack_h2(fmaxf(c[mt][nt][2] + bb0, 0.f), fmaxf(c[mt][nt][3] + bb1, 0.f));
            c[mt][nt][0] = c[mt][nt][1] = c[mt][nt][2] = c[mt][nt][3] = 0.f;
        }

    // ---- GEMM2: D2 = h1 @ W2 (sb=1) ----
    gemm_mma(su, g_W2h, 1, aA, bB, c);

    // ---- epilogue2: relu(D2 + b2), shuffle-reduce, atomicAdd to g_emb ----
    {
        int jl = mw >> 1, sub = mw & 1;
#pragma unroll
        for (int nt = 0; nt < 8; nt++) {
            int col = n0 + nt * 8 + 2 * tig;
            float bb0 = b2s[col], bb1 = b2s[col + 1];
            float s0 = fmaxf(c[0][nt][0] + bb0, 0.f) + fmaxf(c[0][nt][2] + bb0, 0.f) +
                       fmaxf(c[1][nt][0] + bb0, 0.f) + fmaxf(c[1][nt][2] + bb0, 0.f);
            float s1 = fmaxf(c[0][nt][1] + bb1, 0.f) + fmaxf(c[0][nt][3] + bb1, 0.f) +
                       fmaxf(c[1][nt][1] + bb1, 0.f) + fmaxf(c[1][nt][3] + bb1, 0.f);
#pragma unroll
            for (int msk = 4; msk <= 16; msk <<= 1) {
                s0 += __shfl_xor_sync(0xFFFFFFFF, s0, msk);
                s1 += __shfl_xor_sync(0xFFFFFFFF, s1, msk);
            }
            if (gid == 0) {
                red[(jl * 2 + sub) * GH + col] = s0;
                red[(jl * 2 + sub) * GH + col + 1] = s1;
            }
        }
        __syncthreads();
        if (tid < GH) {
            float t = (red[tid] + red[GH + tid]) + (red[2 * GH + tid] + red[3 * GH + tid]);
            atomicAdd(&g_emb[b * GH + tid], t);
        }
    }
}

// ---------------- K3: f MLP (512 threads; k-split phases) --------------------
__global__ __launch_bounds__(512) void f_kernel(const float* __restrict__ fw0,
                                                const float* __restrict__ fb0,
                                                const float* __restrict__ fw1,
                                                const float* __restrict__ fb1,
                                                float* __restrict__ out) {
    __shared__ float e[GH];
    __shared__ float h[GH];
    __shared__ float pa[2][GH];
    __shared__ float red[16 * FOUT];
    int b = blockIdx.x, tid = threadIdx.x;
    int col = tid & 255, half = tid >> 8;

    // phase A: e[n] = sum_j partial-embedding; j split across 2 halves
    {
        const float* p = g_emb;  // note: g_emb already reduced by rn atomics
        (void)p;
    }
    // g_emb is fully reduced; just load it (rn did the j-reduction via atomics)
    if (tid < GH) e[tid] = g_emb[b * GH + tid];
    __syncthreads();

    // phase B: h[n] = relu(e . fw0[:,n] + fb0[n]); k split across 2 halves
    {
        float a[4];
#pragma unroll
        for (int u = 0; u < 4; u++) a[u] = 0.f;
        int k0 = half * 128;
#pragma unroll 4
        for (int k = 0; k < 128; k += 4)
#pragma unroll
            for (int u = 0; u < 4; u++)
                a[u] = fmaf(e[k0 + k + u], fw0[(k0 + k + u) * GH + col], a[u]);
        pa[half][col] = (a[0] + a[1]) + (a[2] + a[3]);
    }
    __syncthreads();
    if (tid < GH) h[tid] = fmaxf(pa[0][tid] + pa[1][tid] + fb0[tid], 0.f);
    __syncthreads();

    // phase C: out = h @ fw1 + fb1, k split across 16 warps
    {
        int w = tid >> 5, lane = tid & 31;
        float ps = 0.f;
#pragma unroll
        for (int kk = 0; kk < 16; kk++) {
            int k = w * 16 + kk;
            ps = fmaf(h[k], fw1[k * FOUT + lane], ps);
        }
        red[w * FOUT + lane] = ps;
        __syncthreads();
        if (tid < FOUT) {
            float a = fb1[tid];
#pragma unroll
            for (int t = 0; t < 16; t++) a += red[t * FOUT + tid];
            out[b * FOUT + tid] = a;
        }
    }
}

// ---------------- launch ----------------------------------------------------
extern "C" void kernel_launch(void* const* d_in, const int* in_sizes, int n_in,
                              void* d_out, int out_size) {
    const float* x   = (const float*)d_in[0];
    const float* q   = (const float*)d_in[1];
    const float* gw0 = (const float*)d_in[2];
    const float* gb0 = (const float*)d_in[3];
    const float* gw1 = (const float*)d_in[4];
    const float* gb1 = (const float*)d_in[5];
    const float* gw2 = (const float*)d_in[6];
    const float* gb2 = (const float*)d_in[7];
    const float* fw0 = (const float*)d_in[8];
    const float* fb0 = (const float*)d_in[9];
    const float* fw1 = (const float*)d_in[10];
    const float* fb1 = (const float*)d_in[11];
    float* out = (float*)d_out;

    cudaFuncSetAttribute(rn_mma_kernel, cudaFuncAttributeMaxDynamicSharedMemorySize, SMEM_TOT);
    cudaFuncSetAttribute(prep_kernel, cudaFuncAttributeMaxDynamicSharedMemorySize, PREP_SMEM);

    prep_kernel<<<640, 256, PREP_SMEM>>>(x, q, gw0, gb0, gw1, gw2);
    rn_mma_kernel<<<BATCH * NFACT / 2, 512, SMEM_TOT>>>(gb1, gb2);
    f_kernel<<<BATCH, 512>>>(fw0, fb0, fw1, fb1, out);
}